// round 12
// baseline (speedup 1.0000x reference)
#include <cuda_runtime.h>
#include <cuda_bf16.h>
#include <cstdint>

// MyConvNet fused, one CTA per image, 256 threads (8 warps), 2 CTAs/SM.
//  conv1+pool1+relu : FFMA packed f32x2, writes Ht (bf16 hi/lo, pos-major)
//  conv2            : mma.sync m16n8k16 bf16, 3-pass (Ah*Bh + Al*Bh + Ah*Bl),
//                     9 shift-GEMMs, fp32 accumulators in registers
//  pool2+relu, conv3: FFMA
// B tiles (image-invariant) pre-packed in fragment-friendly layout by prep_kernel.

typedef unsigned long long ull;

__device__ __forceinline__ ull pack2(float lo, float hi) {
    ull v; asm("mov.b64 %0, {%1, %2};" : "=l"(v) : "f"(lo), "f"(hi)); return v;
}
__device__ __forceinline__ void unpack2(ull v, float& lo, float& hi) {
    asm("mov.b64 {%0, %1}, %2;" : "=f"(lo), "=f"(hi) : "l"(v));
}
__device__ __forceinline__ void fma2(ull& d, ull a, ull b) {
    asm("fma.rn.f32x2 %0, %1, %2, %0;" : "+l"(d) : "l"(a), "l"(b));
}

// D(16x8,f32) += A(16x16,bf16,row) * B(16x8,bf16,col)
__device__ __forceinline__ void mma_bf16(float* d, const uint32_t* a,
                                         uint32_t b0, uint32_t b1) {
    asm volatile(
        "mma.sync.aligned.m16n8k16.row.col.f32.bf16.bf16.f32 "
        "{%0,%1,%2,%3}, {%4,%5,%6,%7}, {%8,%9}, {%0,%1,%2,%3};"
        : "+f"(d[0]), "+f"(d[1]), "+f"(d[2]), "+f"(d[3])
        : "r"(a[0]), "r"(a[1]), "r"(a[2]), "r"(a[3]), "r"(b0), "r"(b1));
}

// ---- smem layout (float offsets) ----
#define X_OFF    0
#define W1_OFF   784
#define B1_OFF   1360
#define B2_OFF   1424
#define HT_HI    1488            // 160 rows x 36 words (bf16x2) = 5760
#define HT_LO    7248            // 5760
#define BS_OFF   13008           // 2 buffers x 4608 words
#define C2_OFF   1488            // alias over Ht after all MMAs: [128 m][66]
#define H2_OFF   13008           // alias over BS after all MMAs: 1024
#define SMEM_FLOATS 22224
#define SMEM_BYTES  (SMEM_FLOATS * 4)
#define NT 256
#define HTW 36                   // words per Ht row (72 bf16, 64 used)

// prebuilt B tiles: [s][pr(hi,lo)][64 oc][36 words] ; word = bf16x2 (ic even, odd)
__device__ __align__(16) uint32_t g_B[9 * 2 * 64 * 36];

__global__ void prep_kernel(const float* __restrict__ w2) {
    const int s = blockIdx.x;                    // shift 0..8
    for (int i = threadIdx.x; i < 2048; i += blockDim.x) {
        const int oc = i >> 5, w = i & 31;       // word w = ic pair (2w, 2w+1)
        const float v0 = w2[oc * 576 + (2 * w) * 9 + s];
        const float v1 = w2[oc * 576 + (2 * w + 1) * 9 + s];
        const __nv_bfloat162 h = __floats2bfloat162_rn(v0, v1);
        const float r0 = v0 - __bfloat162float(h.x);
        const float r1 = v1 - __bfloat162float(h.y);
        const __nv_bfloat162 l = __floats2bfloat162_rn(r0, r1);
        g_B[(s * 2 + 0) * 2304 + oc * HTW + w] = *reinterpret_cast<const uint32_t*>(&h);
        g_B[(s * 2 + 1) * 2304 + oc * HTW + w] = *reinterpret_cast<const uint32_t*>(&l);
    }
}

__global__ void __launch_bounds__(NT, 2)
convnet_kernel(const float* __restrict__ x,
               const float* __restrict__ w1, const float* __restrict__ b1,
               const float* __restrict__ b2,
               const float* __restrict__ w3, const float* __restrict__ b3,
               float* __restrict__ out)
{
    extern __shared__ float sm[];
    const int tid  = threadIdx.x;
    const int img  = blockIdx.x;
    const int wid  = tid >> 5;
    const int lane = tid & 31;
    const int g    = lane >> 2;   // fragment group row
    const int t    = lane & 3;    // fragment thread-in-group

    // ---------------- Phase 0: loads + B(s=0) copy ----------------
    {
        const float* xg = x + img * 784;
        for (int i = tid; i < 784; i += NT) sm[X_OFF + i] = xg[i];
        for (int i = tid; i < 576; i += NT) sm[W1_OFF + i] = w1[i];
        if (tid < 64) { sm[B1_OFF + tid] = b1[tid]; sm[B2_OFF + tid] = b2[tid]; }
        const uint4* src = reinterpret_cast<const uint4*>(g_B);
        uint4* dst = reinterpret_cast<uint4*>(sm + BS_OFF);
        for (int i = tid; i < 1152; i += NT) dst[i] = __ldg(src + i);
    }
    __syncthreads();

    // ------- Phase 1: conv1 + maxpool(3,2) + relu -> Ht bf16 hi/lo -------
    {
        const int ch = tid & 63;
        const int g0 = tid >> 6;   // 0..3
        const float bc = sm[B1_OFF + ch];
        ull wp[9];
        #pragma unroll
        for (int j = 0; j < 9; j++) {
            const float w = sm[W1_OFF + ch * 9 + j];
            wp[j] = pack2(w, w);
        }
        __nv_bfloat16* HHb = reinterpret_cast<__nv_bfloat16*>(sm + HT_HI);
        __nv_bfloat16* HLb = reinterpret_cast<__nv_bfloat16*>(sm + HT_LO);

        #pragma unroll 1
        for (int it = 0; it < 17; it++) {
            const int pr = g0 + 4 * it;        // 0..65
            if (pr < 66) {
                const int py  = pr / 6;            // 0..10
                const int px0 = (pr - py * 6) * 2; // 0..10 even
                const float* xp = sm + X_OFF + (2 * py) * 28 + 2 * px0;
                ull pa[5][5];
                #pragma unroll
                for (int r = 0; r < 5; r++) {
                    float row[7];
                    #pragma unroll
                    for (int c = 0; c < 7; c++) row[c] = xp[r * 28 + c];
                    #pragma unroll
                    for (int c = 0; c < 5; c++) pa[r][c] = pack2(row[c], row[c + 2]);
                }
                float m0 = -3.0e38f, m1 = -3.0e38f;
                #pragma unroll
                for (int dy = 0; dy < 3; dy++)
                    #pragma unroll
                    for (int dx = 0; dx < 3; dx++) {
                        ull s2 = 0ull;
                        #pragma unroll
                        for (int r = 0; r < 3; r++)
                            #pragma unroll
                            for (int cc = 0; cc < 3; cc++)
                                fma2(s2, wp[r * 3 + cc], pa[dy + r][dx + cc]);
                        float s0, s1;
                        unpack2(s2, s0, s1);
                        m0 = fmaxf(m0, s0);
                        m1 = fmaxf(m1, s1);
                    }
                const float v0 = fmaxf(m0 + bc, 0.f);
                const float v1 = fmaxf(m1 + bc, 0.f);
                const int pos = py * 12 + px0;
                const __nv_bfloat16 h0 = __float2bfloat16(v0);
                const __nv_bfloat16 h1 = __float2bfloat16(v1);
                HHb[pos * 72 + ch]       = h0;
                HHb[(pos + 1) * 72 + ch] = h1;
                HLb[pos * 72 + ch]       = __float2bfloat16(v0 - __bfloat162float(h0));
                HLb[(pos + 1) * 72 + ch] = __float2bfloat16(v1 - __bfloat162float(h1));
            }
        }
    }
    __syncthreads();

    // ------- Phase 2: 9 shift-GEMMs on mma.sync bf16 (3-pass split) -------
    float d[8][4];
    #pragma unroll
    for (int nt = 0; nt < 8; nt++)
        #pragma unroll
        for (int q = 0; q < 4; q++) d[nt][q] = 0.f;

    {
        const uint32_t* HH = reinterpret_cast<const uint32_t*>(sm + HT_HI);
        const uint32_t* HL = reinterpret_cast<const uint32_t*>(sm + HT_LO);

        #pragma unroll 1
        for (int s = 0; s < 9; s++) {
            // prefetch next shift's B into the other buffer (visible after bottom sync)
            if (s < 8) {
                const uint4* src = reinterpret_cast<const uint4*>(g_B) + (s + 1) * 1152;
                uint4* dst = reinterpret_cast<uint4*>(sm + BS_OFF) + ((s + 1) & 1) * 1152;
                for (int i = tid; i < 1152; i += NT) dst[i] = __ldg(src + i);
            }

            const int off = 12 * (s / 3) + (s % 3);
            const int rowA = 16 * wid + g + off;
            const uint32_t* pa = HH + rowA * HTW + t;   // hi
            const uint32_t* pl = HL + rowA * HTW + t;   // lo
            const uint32_t* BB = reinterpret_cast<const uint32_t*>(sm + BS_OFF)
                               + (s & 1) * 4608;

            #pragma unroll
            for (int ks = 0; ks < 4; ks++) {
                uint32_t ah[4], al[4];
                ah[0] = pa[ks * 8];            ah[2] = pa[ks * 8 + 4];
                ah[1] = pa[ks * 8 + 8 * HTW];  ah[3] = pa[ks * 8 + 8 * HTW + 4];
                al[0] = pl[ks * 8];            al[2] = pl[ks * 8 + 4];
                al[1] = pl[ks * 8 + 8 * HTW];  al[3] = pl[ks * 8 + 8 * HTW + 4];
                #pragma unroll
                for (int nt = 0; nt < 8; nt++) {
                    const uint32_t* pb = BB + (nt * 8 + g) * HTW + ks * 8 + t;
                    const uint32_t bh0 = pb[0],        bh1 = pb[4];
                    const uint32_t bl0 = pb[2304],     bl1 = pb[2304 + 4];
                    mma_bf16(d[nt], ah, bh0, bh1);
                    mma_bf16(d[nt], al, bh0, bh1);
                    mma_bf16(d[nt], ah, bl0, bl1);
                }
            }
            __syncthreads();
        }
    }

    // ------- D writeout: c2[m][66] = D + b2 (aliases Ht region) -------
    float* c2 = sm + C2_OFF;
    {
        const int row0 = 16 * wid + g;
        #pragma unroll
        for (int nt = 0; nt < 8; nt++) {
            const int oc = nt * 8 + 2 * t;
            const float bb0 = sm[B2_OFF + oc];
            const float bb1 = sm[B2_OFF + oc + 1];
            *reinterpret_cast<float2*>(c2 + row0 * 66 + oc) =
                make_float2(d[nt][0] + bb0, d[nt][1] + bb1);
            *reinterpret_cast<float2*>(c2 + (row0 + 8) * 66 + oc) =
                make_float2(d[nt][2] + bb0, d[nt][3] + bb1);
        }
    }
    __syncthreads();

    // ------- Phase 3: maxpool2(3,2) + relu -> h2 [64][16] (aliases BS) -------
    float* h2 = sm + H2_OFF;
    for (int i = tid; i < 1024; i += NT) {
        const int oc = i >> 4;
        const int p  = i & 15;
        const int j  = p >> 2, ii = p & 3;
        const int m0 = (2 * j) * 12 + 2 * ii;
        float m = -3.0e38f;
        #pragma unroll
        for (int dy = 0; dy < 3; dy++)
            #pragma unroll
            for (int dx = 0; dx < 3; dx++)
                m = fmaxf(m, c2[(m0 + dy * 12 + dx) * 66 + oc]);
        h2[oc * 16 + p] = fmaxf(m, 0.f);
    }
    __syncthreads();

    // ------- Phase 4: conv3 (10 dots over 1024) -------
    for (int o = wid; o < 10; o += 8) {
        const float4* wp = reinterpret_cast<const float4*>(w3 + (o << 10));
        const float4* hp = reinterpret_cast<const float4*>(h2);
        float sres = 0.f;
        #pragma unroll
        for (int m = 0; m < 8; m++) {
            const float4 wv = __ldg(wp + lane + 32 * m);
            const float4 hv = hp[lane + 32 * m];
            sres = fmaf(wv.x, hv.x, sres);
            sres = fmaf(wv.y, hv.y, sres);
            sres = fmaf(wv.z, hv.z, sres);
            sres = fmaf(wv.w, hv.w, sres);
        }
        #pragma unroll
        for (int off = 16; off > 0; off >>= 1)
            sres += __shfl_down_sync(0xffffffffu, sres, off);
        if (lane == 0) out[img * 10 + o] = sres + b3[o];
    }
}

extern "C" void kernel_launch(void* const* d_in, const int* in_sizes, int n_in,
                              void* d_out, int out_size)
{
    const float* x  = (const float*)d_in[0];
    const float* w1 = (const float*)d_in[1];
    const float* b1 = (const float*)d_in[2];
    const float* w2 = (const float*)d_in[3];
    const float* b2 = (const float*)d_in[4];
    const float* w3 = (const float*)d_in[5];
    const float* b3 = (const float*)d_in[6];
    float* out = (float*)d_out;

    const int B = in_sizes[0] / 784;

    cudaFuncSetAttribute(convnet_kernel,
                         cudaFuncAttributeMaxDynamicSharedMemorySize, SMEM_BYTES);

    prep_kernel<<<9, 256>>>(w2);
    convnet_kernel<<<B, NT, SMEM_BYTES>>>(x, w1, b1, b2, w3, b3, out);
}